// round 13
// baseline (speedup 1.0000x reference)
#include <cuda_runtime.h>
#include <cuda_fp16.h>
#include <cstdint>

// Problem constants
#define B_DIM      32
#define S_DIM      2048
#define H_DIM      4096
#define R_DIM      64
#define N_ADAPT    16
#define TILE_M     128
#define KC         64                  // K elements per chunk
#define NCHUNK     (H_DIM / KC)        // 64
#define NTHREADS   256

// w SMEM ring: row stride 72 halves = 144 B; LDS.32 at (g+8j)*72 + 16ks + 2t
// -> banks (36g + t) mod 32 all distinct within a warp: conflict-free.
#define LDH        72
#define W_STAGE_H  (R_DIM * LDH)                  // 4608 halves = 9216 B
#define SMEM_TOTAL (2 * W_STAGE_H * 2)            // 18432 B

// Pre-converted fp16 weights (8 MB static scratch)
__device__ __half g_wh[N_ADAPT * R_DIM * H_DIM];

__device__ __forceinline__ uint32_t f2h2(float lo, float hi) {
    __half2 h = __floats2half2_rn(lo, hi);
    return *(const uint32_t*)&h;
}

__device__ __forceinline__ void cp_async16(uint32_t dst, const void* src) {
    asm volatile("cp.async.cg.shared.global [%0], [%1], 16;"
                 :: "r"(dst), "l"(src) : "memory");
}
#define CP_COMMIT() asm volatile("cp.async.commit_group;" ::: "memory")
#define CP_WAIT0()  asm volatile("cp.async.wait_group 0;" ::: "memory")

__device__ __forceinline__ uint32_t smem_u32(const void* p) {
    uint32_t r;
    asm("{ .reg .u64 t; cvta.to.shared.u64 t, %1; cvt.u32.u64 %0, t; }"
        : "=r"(r) : "l"(p));
    return r;
}

// D (f32) += A (f16, row) * B (f16, col)  -- m16n8k16
__device__ __forceinline__ void mma16816(float* d,
                                         uint32_t a0, uint32_t a1,
                                         uint32_t a2, uint32_t a3,
                                         uint32_t b0, uint32_t b1) {
    asm volatile(
        "mma.sync.aligned.m16n8k16.row.col.f32.f16.f16.f32 "
        "{%0,%1,%2,%3}, {%4,%5,%6,%7}, {%8,%9}, {%0,%1,%2,%3};"
        : "+f"(d[0]), "+f"(d[1]), "+f"(d[2]), "+f"(d[3])
        : "r"(a0), "r"(a1), "r"(a2), "r"(a3), "r"(b0), "r"(b1));
}

// ---- kernel 1: convert all adapter weights f32 -> f16 (RN) ----------------
__global__ void convert_w_kernel(const float4* __restrict__ w) {
    int i = blockIdx.x * blockDim.x + threadIdx.x;   // one float4 each
    float4 v = w[i];
    uint2 p;
    p.x = f2h2(v.x, v.y);
    p.y = f2h2(v.z, v.w);
    ((uint2*)g_wh)[i] = p;
}

// ---- kernel 2: gathered GEMM, raw mma.sync, A direct from gmem ------------
__global__ void __launch_bounds__(NTHREADS, 2)
multilora_mma_direct_kernel(const float* __restrict__ x,
                            const int* __restrict__ adapter_ids,
                            float* __restrict__ out) {
    extern __shared__ __align__(16) __half smw[];    // w ring: 2 stages
    const uint32_t smw_base = smem_u32(smw);

    const int tid  = threadIdx.x;
    const int wid  = tid >> 5;          // 0..7, warp owns rows 16*wid..+15
    const int lane = tid & 31;
    const int g    = lane >> 2;         // 0..7
    const int t    = lane & 3;          // 0..3

    const int mtile = blockIdx.x;       // 0..15
    const int b     = blockIdx.y;       // 0..31
    const int m0    = mtile * TILE_M;
    const int aid   = __ldg(adapter_ids + b);

    // ---- x pointers for this lane's A-fragment sources
    // a0 <- (row g,   k=2t), a1 <- (row g+8, k=2t),
    // a2 <- (row g,   k=2t+8), a3 <- (row g+8, k=2t+8)   [per k-step base]
    const float* pA = x + ((size_t)(b * S_DIM + m0 + 16 * wid + g)) * H_DIM
                        + 2 * t;
    const float* pB = pA + (size_t)8 * H_DIM;

    // ---- w cp.async mapping: 512 16B-copies / chunk over 256 thr = 2 each
    const __half* whbase = g_wh + (size_t)aid * R_DIM * H_DIM;
    const __half* wg[2];
    uint32_t woff[2];
    #pragma unroll
    for (int j = 0; j < 2; j++) {
        int i = tid + j * NTHREADS;
        int row = i >> 3, seg = i & 7;
        wg[j]   = whbase + (size_t)row * H_DIM + seg * 8;
        woff[j] = (uint32_t)((row * LDH + seg * 8) * 2);
    }

    // ---- accumulators: 8 n-tiles x 4 f32 (warp tile 16x64)
    float acc[8][4];
    #pragma unroll
    for (int j = 0; j < 8; j++)
        #pragma unroll
        for (int c = 0; c < 4; c++)
            acc[j][c] = 0.0f;

    // ---- prologue: w(0) into stage 0; x chunk 0 into register stage
    #pragma unroll
    for (int j = 0; j < 2; j++)
        cp_async16(smw_base + woff[j], wg[j]);
    CP_COMMIT();

    float2 xs[16];                      // [ks][4 sources], f32 pairs
    #pragma unroll
    for (int ks = 0; ks < 4; ks++) {
        xs[ks * 4 + 0] = *(const float2*)(pA + ks * 16);
        xs[ks * 4 + 1] = *(const float2*)(pB + ks * 16);
        xs[ks * 4 + 2] = *(const float2*)(pA + ks * 16 + 8);
        xs[ks * 4 + 3] = *(const float2*)(pB + ks * 16 + 8);
    }

    for (int kc = 0; kc < NCHUNK; kc++) {
        const int s = kc & 1;
        const __half* ws = smw + s * W_STAGE_H;

        // convert staged x (chunk kc) to a-fragment registers
        uint32_t a_[16];
        #pragma unroll
        for (int i = 0; i < 16; i++)
            a_[i] = f2h2(xs[i].x, xs[i].y);

        // issue x loads for chunk kc+1 (land during barrier + mma below)
        if (kc + 1 < NCHUNK) {
            const size_t gk = (size_t)(kc + 1) * KC;
            #pragma unroll
            for (int ks = 0; ks < 4; ks++) {
                xs[ks * 4 + 0] = *(const float2*)(pA + gk + ks * 16);
                xs[ks * 4 + 1] = *(const float2*)(pB + gk + ks * 16);
                xs[ks * 4 + 2] = *(const float2*)(pA + gk + ks * 16 + 8);
                xs[ks * 4 + 3] = *(const float2*)(pB + gk + ks * 16 + 8);
            }
        }

        // w(kc) must be resident; barrier also proves all warps finished
        // reading stage s^1 (mma of kc-1) -> safe to overwrite below.
        CP_WAIT0();
        __syncthreads();

        if (kc + 1 < NCHUNK) {
            const uint32_t sb1 = smw_base + (s ^ 1) * W_STAGE_H * 2;
            #pragma unroll
            for (int j = 0; j < 2; j++)
                cp_async16(sb1 + woff[j], wg[j] + (size_t)(kc + 1) * KC);
        }
        CP_COMMIT();

        // mma: 4 k-steps x 8 n-tiles; b via conflict-free LDS.32
        #pragma unroll
        for (int ks = 0; ks < 4; ks++) {
            const __half* wk = ws + ks * 16 + 2 * t;
            #pragma unroll
            for (int j = 0; j < 8; j++) {
                const __half* bp = wk + (g + 8 * j) * LDH;
                uint32_t b0 = *(const uint32_t*)bp;        // k=2t,2t+1 @ n=g+8j
                uint32_t b1 = *(const uint32_t*)(bp + 8);  // k=2t+8,2t+9
                mma16816(acc[j],
                         a_[ks * 4 + 0], a_[ks * 4 + 1],
                         a_[ks * 4 + 2], a_[ks * 4 + 3],
                         b0, b1);
            }
        }
    }

    // ---- epilogue: direct f32 stores, out is [B, S, R] row-major
    // d0,d1 = (row g, col 2t,2t+1); d2,d3 = (row g+8, same cols)
    float* o0 = out + ((size_t)(b * S_DIM + m0 + 16 * wid + g)) * R_DIM + 2 * t;
    float* o8 = o0 + (size_t)8 * R_DIM;
    #pragma unroll
    for (int j = 0; j < 8; j++) {
        *(float2*)(o0 + 8 * j) = make_float2(acc[j][0], acc[j][1]);
        *(float2*)(o8 + 8 * j) = make_float2(acc[j][2], acc[j][3]);
    }
}

extern "C" void kernel_launch(void* const* d_in, const int* in_sizes, int n_in,
                              void* d_out, int out_size) {
    const float* x   = (const float*)d_in[0];
    const int*   ids = (const int*)d_in[1];
    const float* w   = (const float*)d_in[2];
    float* out = (float*)d_out;

    const int b = in_sizes[1];   // number of requests (32)

    // 1) convert adapter weights f32 -> f16 once per launch
    const int n4 = (N_ADAPT * R_DIM * H_DIM) / 4;    // 1,048,576 float4s
    convert_w_kernel<<<n4 / 256, 256>>>((const float4*)w);

    // 2) main gathered GEMM
    cudaFuncSetAttribute(multilora_mma_direct_kernel,
                         cudaFuncAttributeMaxDynamicSharedMemorySize, SMEM_TOTAL);
    dim3 grid(S_DIM / TILE_M, b);
    multilora_mma_direct_kernel<<<grid, NTHREADS, SMEM_TOTAL>>>(x, ids, out);
}

// round 14
// speedup vs baseline: 1.4491x; 1.4491x over previous
#include <cuda_runtime.h>
#include <cuda_fp16.h>
#include <mma.h>
#include <cstdint>

using namespace nvcuda;

// Problem constants
#define B_DIM      32
#define S_DIM      2048
#define H_DIM      4096
#define R_DIM      64
#define N_ADAPT    16
#define TILE_M     128
#define KC         64
#define KSPLIT     4
#define NCHUNK_PER (H_DIM / KC / KSPLIT)   // 16 chunks per CTA
#define NTILES     ((S_DIM / TILE_M) * B_DIM)  // 512
#define TILE_ELEMS (TILE_M * R_DIM)        // 8192
#define NTHREADS   256

// SMEM (half): row stride 72 halves = 144 B (conflict-free, ldm mult of 8)
#define LDH        72
#define X_STAGE_H  (TILE_M * LDH)                 // 18432 B
#define W_STAGE_H  (R_DIM * LDH)                  // 9216 B
#define STAGE_H    (X_STAGE_H + W_STAGE_H)
#define STAGE_B    (STAGE_H * 2)                  // 27648 B
#define SMEM_TOTAL (2 * STAGE_B)                  // 55296 B (x2 CTAs = 110592)

// Static scratch: fp16 weights (8 MB), split-K partials (67 MB), counters
__device__ __half g_wh[N_ADAPT * R_DIM * H_DIM];
__device__ float  g_part[NTILES * KSPLIT * TILE_ELEMS];
__device__ int    g_cnt[NTILES];   // zero-init at load; reset by reducer

__device__ __forceinline__ uint32_t smem_u32(const void* p) {
    uint32_t r;
    asm("{ .reg .u64 t; cvta.to.shared.u64 t, %1; cvt.u32.u64 %0, t; }"
        : "=r"(r) : "l"(p));
    return r;
}

__device__ __forceinline__ void sts64(uint32_t addr, uint32_t a, uint32_t b) {
    asm volatile("st.shared.v2.b32 [%0], {%1, %2};"
                 :: "r"(addr), "r"(a), "r"(b));
}

__device__ __forceinline__ void cp_async16(uint32_t dst, const void* src) {
    asm volatile("cp.async.cg.shared.global [%0], [%1], 16;"
                 :: "r"(dst), "l"(src) : "memory");
}
#define CP_COMMIT() asm volatile("cp.async.commit_group;" ::: "memory")
#define CP_WAIT0()  asm volatile("cp.async.wait_group 0;" ::: "memory")

// ---- kernel 1: convert all adapter weights f32 -> f16 (RN) ----------------
__global__ void convert_w_kernel(const float4* __restrict__ w) {
    int i = blockIdx.x * blockDim.x + threadIdx.x;
    float4 v = w[i];
    __half2 h0 = __floats2half2_rn(v.x, v.y);
    __half2 h1 = __floats2half2_rn(v.z, v.w);
    uint2 p;
    p.x = *(const uint32_t*)&h0;
    p.y = *(const uint32_t*)&h1;
    ((uint2*)g_wh)[i] = p;
}

// ---- kernel 2: gathered GEMM, split-K=4, fused counter reduce --------------
__global__ void __launch_bounds__(NTHREADS, 2)
multilora_fp16_fsk_kernel(const float* __restrict__ x,
                          const int* __restrict__ adapter_ids,
                          float* __restrict__ out) {
    extern __shared__ __align__(16) __half smem[];
    __shared__ int s_last;
    const uint32_t smem_base = smem_u32(smem);

    const int tid = threadIdx.x;
    const int wid = tid >> 5;

    const int kz    = blockIdx.x;       // 0..3  (fastest -> siblings adjacent)
    const int mtile = blockIdx.y;       // 0..15
    const int b     = blockIdx.z;       // 0..31
    const int m0    = mtile * TILE_M;
    const int aid   = __ldg(adapter_ids + b);
    const int tile  = b * (S_DIM / TILE_M) + mtile;   // 0..511
    const size_t k0 = (size_t)kz * NCHUNK_PER * KC;

    // ---- x producer mapping: 2048 float4 quads / chunk over 256 thr = 8 each
    const float* xg[8];
    uint32_t xoff[8];
    #pragma unroll
    for (int j = 0; j < 8; j++) {
        int i = tid + j * NTHREADS;
        int row = i >> 4, q = i & 15;
        xg[j]   = x + ((size_t)(b * S_DIM + m0 + row)) * H_DIM + k0 + q * 4;
        xoff[j] = (uint32_t)((row * LDH + q * 4) * 2);
    }

    // ---- w cp.async mapping: 512 16B-copies / chunk over 256 thr = 2 each
    const __half* whbase = g_wh + (size_t)aid * R_DIM * H_DIM + k0;
    const __half* wg[2];
    uint32_t woff[2];
    #pragma unroll
    for (int j = 0; j < 2; j++) {
        int i = tid + j * NTHREADS;
        int row = i >> 3, seg = i & 7;
        wg[j]   = whbase + (size_t)row * H_DIM + seg * 8;
        woff[j] = (uint32_t)((X_STAGE_H + row * LDH + seg * 8) * 2);
    }

    // ---- consumer mapping: 8 warps, 32x32 warp tiles
    const int wm = wid >> 1;
    const int wn = wid & 1;

    wmma::fragment<wmma::accumulator, 16, 16, 16, float> acc[2][2];
    #pragma unroll
    for (int fi = 0; fi < 2; fi++)
        #pragma unroll
        for (int fj = 0; fj < 2; fj++)
            wmma::fill_fragment(acc[fi][fj], 0.0f);

    // ---- prologue
    #pragma unroll
    for (int j = 0; j < 2; j++)
        cp_async16(smem_base + woff[j], wg[j]);
    CP_COMMIT();

    float4 cur[8];
    #pragma unroll
    for (int j = 0; j < 8; j++)
        cur[j] = *(const float4*)(xg[j]);

    for (int kc = 0; kc < NCHUNK_PER; kc++) {
        const int s = kc & 1;
        const uint32_t sb = smem_base + s * STAGE_B;
        __half* xs = smem + s * STAGE_H;
        __half* ws = xs + X_STAGE_H;

        #pragma unroll
        for (int j = 0; j < 8; j++) {
            __half2 h0 = __floats2half2_rn(cur[j].x, cur[j].y);
            __half2 h1 = __floats2half2_rn(cur[j].z, cur[j].w);
            sts64(sb + xoff[j],
                  *(const uint32_t*)&h0, *(const uint32_t*)&h1);
        }

        if (kc + 1 < NCHUNK_PER) {
            #pragma unroll
            for (int j = 0; j < 8; j++)
                cur[j] = *(const float4*)(xg[j] + (size_t)(kc + 1) * KC);
        }

        CP_WAIT0();
        __syncthreads();

        if (kc + 1 < NCHUNK_PER) {
            const uint32_t sb1 = smem_base + (s ^ 1) * STAGE_B;
            #pragma unroll
            for (int j = 0; j < 2; j++)
                cp_async16(sb1 + woff[j], wg[j] + (size_t)(kc + 1) * KC);
        }
        CP_COMMIT();

        #pragma unroll
        for (int kk = 0; kk < KC; kk += 16) {
            wmma::fragment<wmma::matrix_a, 16, 16, 16, __half,
                           wmma::row_major> af[2];
            wmma::fragment<wmma::matrix_b, 16, 16, 16, __half,
                           wmma::col_major> bf[2];
            #pragma unroll
            for (int fi = 0; fi < 2; fi++)
                wmma::load_matrix_sync(af[fi],
                    xs + (wm * 32 + fi * 16) * LDH + kk, LDH);
            #pragma unroll
            for (int fj = 0; fj < 2; fj++)
                wmma::load_matrix_sync(bf[fj],
                    ws + (wn * 32 + fj * 16) * LDH + kk, LDH);
            #pragma unroll
            for (int fi = 0; fi < 2; fi++)
                #pragma unroll
                for (int fj = 0; fj < 2; fj++)
                    wmma::mma_sync(acc[fi][fj], af[fi], bf[fj], acc[fi][fj]);
        }
    }

    // ---- epilogue A: write this CTA's partial tile to scratch
    float* part = g_part + ((size_t)tile * KSPLIT + kz) * TILE_ELEMS;
    #pragma unroll
    for (int fi = 0; fi < 2; fi++)
        #pragma unroll
        for (int fj = 0; fj < 2; fj++)
            wmma::store_matrix_sync(
                part + (wm * 32 + fi * 16) * R_DIM + wn * 32 + fj * 16,
                acc[fi][fj], R_DIM, wmma::mem_row_major);

    // ---- epilogue B: last arriver reduces the 4 partials (deterministic sum)
    __threadfence();
    __syncthreads();
    if (tid == 0)
        s_last = (atomicAdd(&g_cnt[tile], 1) == KSPLIT - 1);
    __syncthreads();

    if (s_last) {
        __threadfence();   // acquire: make siblings' partials visible
        const float4* p = (const float4*)(g_part +
                          (size_t)tile * KSPLIT * TILE_ELEMS);
        float4* obase = (float4*)(out + ((size_t)(b * S_DIM + m0)) * R_DIM);
        #pragma unroll
        for (int j = 0; j < 8; j++) {
            int idx = tid + j * NTHREADS;            // 0..2047 float4s
            float4 s0 = p[idx];
            float4 s1 = p[idx + TILE_ELEMS / 4];
            float4 s2 = p[idx + 2 * (TILE_ELEMS / 4)];
            float4 s3 = p[idx + 3 * (TILE_ELEMS / 4)];
            float4 r;
            r.x = (s0.x + s1.x) + (s2.x + s3.x);
            r.y = (s0.y + s1.y) + (s2.y + s3.y);
            r.z = (s0.z + s1.z) + (s2.z + s3.z);
            r.w = (s0.w + s1.w) + (s2.w + s3.w);
            obase[idx] = r;
        }
        if (tid == 0) g_cnt[tile] = 0;   // reset for next graph replay
    }
}

extern "C" void kernel_launch(void* const* d_in, const int* in_sizes, int n_in,
                              void* d_out, int out_size) {
    const float* x   = (const float*)d_in[0];
    const int*   ids = (const int*)d_in[1];
    const float* w   = (const float*)d_in[2];
    float* out = (float*)d_out;

    // 1) convert adapter weights f32 -> f16 once per launch
    const int n4 = (N_ADAPT * R_DIM * H_DIM) / 4;
    convert_w_kernel<<<n4 / 256, 256>>>((const float4*)w);

    // 2) gathered GEMM, split-K=4, fused reduce
    cudaFuncSetAttribute(multilora_fp16_fsk_kernel,
                         cudaFuncAttributeMaxDynamicSharedMemorySize, SMEM_TOTAL);
    dim3 grid(KSPLIT, S_DIM / TILE_M, B_DIM);
    multilora_fp16_fsk_kernel<<<grid, NTHREADS, SMEM_TOTAL>>>(x, ids, out);
}

// round 15
// speedup vs baseline: 1.5109x; 1.0426x over previous
#include <cuda_runtime.h>
#include <cuda_fp16.h>
#include <mma.h>
#include <cstdint>

using namespace nvcuda;

// Problem constants
#define B_DIM      32
#define S_DIM      2048
#define H_DIM      4096
#define R_DIM      64
#define N_ADAPT    16
#define TILE_M     128
#define KC         64
#define NCHUNK     (H_DIM / KC)            // 64 chunks per tile
#define NTILES     (B_DIM * (S_DIM / TILE_M))  // 512
#define TOTAL_U    (NTILES * NCHUNK)       // 32768 work units
#define NCTA       296                     // exactly one wave (2/SM x 148)
#define TILE_ELEMS (TILE_M * R_DIM)        // 8192
#define NTHREADS   256

// SMEM (half): row stride 72 halves = 144 B (conflict-free, ldm mult of 8)
#define LDH        72
#define X_STAGE_H  (TILE_M * LDH)
#define W_STAGE_H  (R_DIM * LDH)
#define STAGE_H    (X_STAGE_H + W_STAGE_H)
#define STAGE_B    (STAGE_H * 2)           // 27648 B
#define SMEM_TOTAL (2 * STAGE_B)           // 55296 B (x2 CTAs = 110592)

// Static scratch: fp16 weights (8 MB), 2 partial slots per tile (33.5 MB)
__device__ __half g_wh[N_ADAPT * R_DIM * H_DIM];
__device__ float  g_part[NTILES * 2 * TILE_ELEMS];
__device__ int    g_cnt[NTILES];           // zero at load; reducer resets

__device__ __forceinline__ uint32_t smem_u32(const void* p) {
    uint32_t r;
    asm("{ .reg .u64 t; cvta.to.shared.u64 t, %1; cvt.u32.u64 %0, t; }"
        : "=r"(r) : "l"(p));
    return r;
}

__device__ __forceinline__ void sts64(uint32_t addr, uint32_t a, uint32_t b) {
    asm volatile("st.shared.v2.b32 [%0], {%1, %2};"
                 :: "r"(addr), "r"(a), "r"(b));
}

__device__ __forceinline__ void cp_async16(uint32_t dst, const void* src) {
    asm volatile("cp.async.cg.shared.global [%0], [%1], 16;"
                 :: "r"(dst), "l"(src) : "memory");
}
#define CP_COMMIT() asm volatile("cp.async.commit_group;" ::: "memory")
#define CP_WAIT0()  asm volatile("cp.async.wait_group 0;" ::: "memory")

// ---- kernel 1: convert all adapter weights f32 -> f16 (RN) ----------------
__global__ void convert_w_kernel(const float4* __restrict__ w) {
    int i = blockIdx.x * blockDim.x + threadIdx.x;
    float4 v = w[i];
    __half2 h0 = __floats2half2_rn(v.x, v.y);
    __half2 h1 = __floats2half2_rn(v.z, v.w);
    uint2 p;
    p.x = *(const uint32_t*)&h0;
    p.y = *(const uint32_t*)&h1;
    ((uint2*)g_wh)[i] = p;
}

// ---- kernel 2: Stream-K gathered GEMM --------------------------------------
__global__ void __launch_bounds__(NTHREADS, 2)
multilora_streamk_kernel(const float* __restrict__ x,
                         const int* __restrict__ adapter_ids,
                         float* __restrict__ out) {
    extern __shared__ __align__(16) __half smem[];
    __shared__ int s_last;
    const uint32_t smem_base = smem_u32(smem);

    const int tid = threadIdx.x;
    const int wid = tid >> 5;
    const int cta = blockIdx.x;

    // this CTA's unit range (units = (tile, chunk), chunk-major within tile)
    const int u0 = (int)(((long long)cta * TOTAL_U) / NCTA);
    const int u1 = (int)(((long long)(cta + 1) * TOTAL_U) / NCTA);

    // tid-only (tile-invariant) mappings
    uint32_t xoff[8];
    #pragma unroll
    for (int j = 0; j < 8; j++) {
        int i = tid + j * NTHREADS;
        int row = i >> 4, q = i & 15;
        xoff[j] = (uint32_t)((row * LDH + q * 4) * 2);
    }
    uint32_t woff[2];
    int wrow[2], wseg[2];
    #pragma unroll
    for (int j = 0; j < 2; j++) {
        int i = tid + j * NTHREADS;
        wrow[j] = i >> 3;
        wseg[j] = i & 7;
        woff[j] = (uint32_t)((X_STAGE_H + wrow[j] * LDH + wseg[j] * 8) * 2);
    }

    const int wm = wid >> 1;
    const int wn = wid & 1;

    for (int t = (u0 >> 6); t * NCHUNK < u1; t++) {
        const int base = t * NCHUNK;
        const int c0 = (u0 > base) ? (u0 - base) : 0;
        const int c1 = (base + NCHUNK < u1) ? NCHUNK : (u1 - base);
        const int nch = c1 - c0;

        const int b     = t >> 4;               // 16 m-tiles per batch
        const int mtile = t & 15;
        const int m0    = mtile * TILE_M;
        const int aid   = __ldg(adapter_ids + b);
        const size_t koff = (size_t)c0 * KC;

        // per-tile pointers
        const float* xg[8];
        #pragma unroll
        for (int j = 0; j < 8; j++) {
            int i = tid + j * NTHREADS;
            int row = i >> 4, q = i & 15;
            xg[j] = x + ((size_t)(b * S_DIM + m0 + row)) * H_DIM + koff + q * 4;
        }
        const __half* whb = g_wh + (size_t)aid * R_DIM * H_DIM + koff;
        const __half* wg[2];
        #pragma unroll
        for (int j = 0; j < 2; j++)
            wg[j] = whb + (size_t)wrow[j] * H_DIM + wseg[j] * 8;

        wmma::fragment<wmma::accumulator, 16, 16, 16, float> acc[2][2];
        #pragma unroll
        for (int fi = 0; fi < 2; fi++)
            #pragma unroll
            for (int fj = 0; fj < 2; fj++)
                wmma::fill_fragment(acc[fi][fj], 0.0f);

        // fragment prologue: w(local 0) -> stage 0; x(local 0) -> regs
        #pragma unroll
        for (int j = 0; j < 2; j++)
            cp_async16(smem_base + woff[j], wg[j]);
        CP_COMMIT();

        float4 cur[8];
        #pragma unroll
        for (int j = 0; j < 8; j++)
            cur[j] = *(const float4*)(xg[j]);

        for (int kc = 0; kc < nch; kc++) {
            const int s = kc & 1;
            const uint32_t sb = smem_base + s * STAGE_B;
            __half* xs = smem + s * STAGE_H;
            __half* ws = xs + X_STAGE_H;

            #pragma unroll
            for (int j = 0; j < 8; j++) {
                __half2 h0 = __floats2half2_rn(cur[j].x, cur[j].y);
                __half2 h1 = __floats2half2_rn(cur[j].z, cur[j].w);
                sts64(sb + xoff[j],
                      *(const uint32_t*)&h0, *(const uint32_t*)&h1);
            }

            if (kc + 1 < nch) {
                #pragma unroll
                for (int j = 0; j < 8; j++)
                    cur[j] = *(const float4*)(xg[j] + (size_t)(kc + 1) * KC);
            }

            CP_WAIT0();
            __syncthreads();

            if (kc + 1 < nch) {
                const uint32_t sb1 = smem_base + (s ^ 1) * STAGE_B;
                #pragma unroll
                for (int j = 0; j < 2; j++)
                    cp_async16(sb1 + woff[j], wg[j] + (size_t)(kc + 1) * KC);
            }
            CP_COMMIT();

            #pragma unroll
            for (int kk = 0; kk < KC; kk += 16) {
                wmma::fragment<wmma::matrix_a, 16, 16, 16, __half,
                               wmma::row_major> af[2];
                wmma::fragment<wmma::matrix_b, 16, 16, 16, __half,
                               wmma::col_major> bf[2];
                #pragma unroll
                for (int fi = 0; fi < 2; fi++)
                    wmma::load_matrix_sync(af[fi],
                        xs + (wm * 32 + fi * 16) * LDH + kk, LDH);
                #pragma unroll
                for (int fj = 0; fj < 2; fj++)
                    wmma::load_matrix_sync(bf[fj],
                        ws + (wn * 32 + fj * 16) * LDH + kk, LDH);
                #pragma unroll
                for (int fi = 0; fi < 2; fi++)
                    #pragma unroll
                    for (int fj = 0; fj < 2; fj++)
                        wmma::mma_sync(acc[fi][fj], af[fi], bf[fj],
                                       acc[fi][fj]);
            }
        }

        // ---- fragment epilogue
        if (nch == NCHUNK) {
            // whole tile: store directly
            float* obase = out + ((size_t)(b * S_DIM + m0 + wm * 32)) * R_DIM
                               + wn * 32;
            #pragma unroll
            for (int fi = 0; fi < 2; fi++)
                #pragma unroll
                for (int fj = 0; fj < 2; fj++)
                    wmma::store_matrix_sync(
                        obase + (size_t)fi * 16 * R_DIM + fj * 16,
                        acc[fi][fj], R_DIM, wmma::mem_row_major);
        } else {
            // split tile: exactly 2 fragments exist. slot0 = head (c0==0).
            const int slot = (c0 == 0) ? 0 : 1;
            float* part = g_part + ((size_t)t * 2 + slot) * TILE_ELEMS;
            #pragma unroll
            for (int fi = 0; fi < 2; fi++)
                #pragma unroll
                for (int fj = 0; fj < 2; fj++)
                    wmma::store_matrix_sync(
                        part + (wm * 32 + fi * 16) * R_DIM + wn * 32 + fj * 16,
                        acc[fi][fj], R_DIM, wmma::mem_row_major);

            __threadfence();                 // release partial
            __syncthreads();
            if (tid == 0)
                s_last = (atomicAdd(&g_cnt[t], 1) == 1);
            __syncthreads();

            if (s_last) {
                __threadfence();             // acquire sibling's partial
                const float4* p0 = (const float4*)(g_part +
                                   (size_t)t * 2 * TILE_ELEMS);
                const float4* p1 = p0 + TILE_ELEMS / 4;
                float4* obase = (float4*)(out +
                                ((size_t)(b * S_DIM + m0)) * R_DIM);
                #pragma unroll
                for (int j = 0; j < 8; j++) {
                    int idx = tid + j * NTHREADS;     // 0..2047 float4s
                    float4 a = p0[idx];
                    float4 c = p1[idx];
                    float4 r;
                    r.x = a.x + c.x; r.y = a.y + c.y;
                    r.z = a.z + c.z; r.w = a.w + c.w;
                    obase[idx] = r;
                }
                if (tid == 0) g_cnt[t] = 0;  // reset for graph replay
            }
        }

        // protect smem stages before next fragment overwrites them
        __syncthreads();
    }
}

extern "C" void kernel_launch(void* const* d_in, const int* in_sizes, int n_in,
                              void* d_out, int out_size) {
    const float* x   = (const float*)d_in[0];
    const int*   ids = (const int*)d_in[1];
    const float* w   = (const float*)d_in[2];
    float* out = (float*)d_out;

    // 1) convert adapter weights f32 -> f16 once per launch
    const int n4 = (N_ADAPT * R_DIM * H_DIM) / 4;
    convert_w_kernel<<<n4 / 256, 256>>>((const float4*)w);

    // 2) Stream-K gathered GEMM: one perfectly balanced wave
    cudaFuncSetAttribute(multilora_streamk_kernel,
                         cudaFuncAttributeMaxDynamicSharedMemorySize, SMEM_TOTAL);
    multilora_streamk_kernel<<<NCTA, NTHREADS, SMEM_TOTAL>>>(x, ids, out);
}

// round 16
// speedup vs baseline: 1.6252x; 1.0756x over previous
#include <cuda_runtime.h>
#include <cuda_fp16.h>
#include <mma.h>
#include <cstdint>

using namespace nvcuda;

// Problem constants
#define B_DIM      32
#define S_DIM      2048
#define H_DIM      4096
#define R_DIM      64
#define N_ADAPT    16
#define TILE_M     128
#define KC         64                  // K elements per chunk (locked: R8 win)
#define NCHUNK     (H_DIM / KC)        // 64
#define NTHREADS   256

// SMEM (half): row stride 72 halves = 144 B (conflict-free, ldm mult of 8)
#define LDH        72
#define X_STAGE_H  (TILE_M * LDH)                 // 9216 halves = 18432 B
#define W_STAGE_H  (R_DIM * LDH)                  // 4608 halves = 9216 B
#define STAGE_H    (X_STAGE_H + W_STAGE_H)        // 13824 halves
#define STAGE_B    (STAGE_H * 2)                  // 27648 B
#define SMEM_TOTAL (2 * STAGE_B)                  // 55296 B (x2 CTAs = 110592)

// Pre-converted fp16 weights (8 MB static scratch)
__device__ __half g_wh[N_ADAPT * R_DIM * H_DIM];

__device__ __forceinline__ uint32_t smem_u32(const void* p) {
    uint32_t r;
    asm("{ .reg .u64 t; cvta.to.shared.u64 t, %1; cvt.u32.u64 %0, t; }"
        : "=r"(r) : "l"(p));
    return r;
}

__device__ __forceinline__ void sts64(uint32_t addr, uint32_t a, uint32_t b) {
    asm volatile("st.shared.v2.b32 [%0], {%1, %2};"
                 :: "r"(addr), "r"(a), "r"(b));
}

__device__ __forceinline__ void cp_async16(uint32_t dst, const void* src) {
    asm volatile("cp.async.cg.shared.global [%0], [%1], 16;"
                 :: "r"(dst), "l"(src) : "memory");
}
#define CP_COMMIT() asm volatile("cp.async.commit_group;" ::: "memory")
#define CP_WAIT0()  asm volatile("cp.async.wait_group 0;" ::: "memory")

// ---- kernel 1: convert adapter weights f32 -> f16 (RN), MLP-4 streaming ----
// 1024 blocks x 256 threads x 4 block-strided float4 each: 4 independent
// fully-coalesced LDG.128 in flight per thread -> latency fully overlapped.
__global__ void __launch_bounds__(256, 8)
convert_w_kernel(const float4* __restrict__ w) {
    const int base = blockIdx.x * 1024 + threadIdx.x;
    float4 v[4];
    #pragma unroll
    for (int j = 0; j < 4; j++)
        v[j] = w[base + j * 256];
    #pragma unroll
    for (int j = 0; j < 4; j++) {
        __half2 h0 = __floats2half2_rn(v[j].x, v[j].y);
        __half2 h1 = __floats2half2_rn(v[j].z, v[j].w);
        uint2 p;
        p.x = *(const uint32_t*)&h0;
        p.y = *(const uint32_t*)&h1;
        ((uint2*)g_wh)[base + j * 256] = p;
    }
}

// ---- kernel 2: gathered GEMM, fp16 HMMA, KC=64, w via cp.async (R11) ------
__global__ void __launch_bounds__(NTHREADS, 2)
multilora_fp16_wasync_kernel(const float* __restrict__ x,
                             const int* __restrict__ adapter_ids,
                             float* __restrict__ out) {
    extern __shared__ __align__(16) __half smem[];
    const uint32_t smem_base = smem_u32(smem);

    const int tid = threadIdx.x;
    const int wid = tid >> 5;

    const int mtile = blockIdx.x;       // 0..15
    const int b     = blockIdx.y;       // 0..31
    const int m0    = mtile * TILE_M;
    const int aid   = __ldg(adapter_ids + b);

    // ---- x producer mapping: 2048 float4 quads / chunk over 256 thr = 8 each
    const float* xg[8];
    uint32_t xoff[8];
    #pragma unroll
    for (int j = 0; j < 8; j++) {
        int i = tid + j * NTHREADS;
        int row = i >> 4, q = i & 15;
        xg[j]   = x + ((size_t)(b * S_DIM + m0 + row)) * H_DIM + q * 4;
        xoff[j] = (uint32_t)((row * LDH + q * 4) * 2);
    }

    // ---- w cp.async mapping: 512 16B-copies / chunk over 256 thr = 2 each
    const __half* whbase = g_wh + (size_t)aid * R_DIM * H_DIM;
    const __half* wg[2];
    uint32_t woff[2];
    #pragma unroll
    for (int j = 0; j < 2; j++) {
        int i = tid + j * NTHREADS;
        int row = i >> 3, seg = i & 7;
        wg[j]   = whbase + (size_t)row * H_DIM + seg * 8;
        woff[j] = (uint32_t)((X_STAGE_H + row * LDH + seg * 8) * 2);
    }

    // ---- consumer mapping: 8 warps, 32x32 warp tiles (4 along M, 2 along N)
    const int wm = wid >> 1;
    const int wn = wid & 1;

    wmma::fragment<wmma::accumulator, 16, 16, 16, float> acc[2][2];
    #pragma unroll
    for (int fi = 0; fi < 2; fi++)
        #pragma unroll
        for (int fj = 0; fj < 2; fj++)
            wmma::fill_fragment(acc[fi][fj], 0.0f);

    // ---- prologue: w(0) into stage 0 via cp.async; x(0) into registers
    #pragma unroll
    for (int j = 0; j < 2; j++)
        cp_async16(smem_base + woff[j], wg[j]);
    CP_COMMIT();

    float4 cur[8];
    #pragma unroll
    for (int j = 0; j < 8; j++)
        cur[j] = *(const float4*)(xg[j]);

    for (int kc = 0; kc < NCHUNK; kc++) {
        const int s = kc & 1;
        const uint32_t sb = smem_base + s * STAGE_B;
        __half* xs = smem + s * STAGE_H;
        __half* ws = xs + X_STAGE_H;

        // x: RN convert + STS.64 (empties cur)
        #pragma unroll
        for (int j = 0; j < 8; j++) {
            __half2 h0 = __floats2half2_rn(cur[j].x, cur[j].y);
            __half2 h1 = __floats2half2_rn(cur[j].z, cur[j].w);
            sts64(sb + xoff[j],
                  *(const uint32_t*)&h0, *(const uint32_t*)&h1);
        }

        // x loads for chunk kc+1 (land during barrier + 4 k-steps below)
        if (kc + 1 < NCHUNK) {
            #pragma unroll
            for (int j = 0; j < 8; j++)
                cur[j] = *(const float4*)(xg[j] + (size_t)(kc + 1) * KC);
        }

        // w(kc) must be resident (only group(kc) can still be pending)
        CP_WAIT0();

        // Barrier: RAW on stage s (x STS + w cp.async visible to all);
        // also proves WMMA(kc-1) done -> stage s^1 writable below.
        __syncthreads();

        // w(kc+1) via cp.async into stage s^1
        if (kc + 1 < NCHUNK) {
            const uint32_t sb1 = smem_base + (s ^ 1) * STAGE_B;
            #pragma unroll
            for (int j = 0; j < 2; j++)
                cp_async16(sb1 + woff[j], wg[j] + (size_t)(kc + 1) * KC);
        }
        CP_COMMIT();

        // compute: 4 k-steps of m16n16k16
        #pragma unroll
        for (int kk = 0; kk < KC; kk += 16) {
            wmma::fragment<wmma::matrix_a, 16, 16, 16, __half,
                           wmma::row_major> af[2];
            wmma::fragment<wmma::matrix_b, 16, 16, 16, __half,
                           wmma::col_major> bf[2];
            #pragma unroll
            for (int fi = 0; fi < 2; fi++)
                wmma::load_matrix_sync(af[fi],
                    xs + (wm * 32 + fi * 16) * LDH + kk, LDH);
            #pragma unroll
            for (int fj = 0; fj < 2; fj++)
                wmma::load_matrix_sync(bf[fj],
                    ws + (wn * 32 + fj * 16) * LDH + kk, LDH);
            #pragma unroll
            for (int fi = 0; fi < 2; fi++)
                #pragma unroll
                for (int fj = 0; fj < 2; fj++)
                    wmma::mma_sync(acc[fi][fj], af[fi], bf[fj], acc[fi][fj]);
        }
    }

    // ---- epilogue: direct store to gmem, out is [B, S, R] row-major
    float* obase = out + ((size_t)(b * S_DIM + m0 + wm * 32)) * R_DIM + wn * 32;
    #pragma unroll
    for (int fi = 0; fi < 2; fi++)
        #pragma unroll
        for (int fj = 0; fj < 2; fj++)
            wmma::store_matrix_sync(obase + (size_t)fi * 16 * R_DIM + fj * 16,
                                    acc[fi][fj], R_DIM, wmma::mem_row_major);
}

extern "C" void kernel_launch(void* const* d_in, const int* in_sizes, int n_in,
                              void* d_out, int out_size) {
    const float* x   = (const float*)d_in[0];
    const int*   ids = (const int*)d_in[1];
    const float* w   = (const float*)d_in[2];
    float* out = (float*)d_out;

    const int b = in_sizes[1];   // number of requests (32)

    // 1) convert adapter weights f32 -> f16 (MLP-4 streaming, ~4.3 us)
    const int n4 = (N_ADAPT * R_DIM * H_DIM) / 4;    // 1,048,576 float4s
    convert_w_kernel<<<n4 / 1024, 256>>>((const float4*)w);

    // 2) main gathered GEMM (R11 structure, committed winner)
    cudaFuncSetAttribute(multilora_fp16_wasync_kernel,
                         cudaFuncAttributeMaxDynamicSharedMemorySize, SMEM_TOTAL);
    dim3 grid(S_DIM / TILE_M, b);
    multilora_fp16_wasync_kernel<<<grid, NTHREADS, SMEM_TOTAL>>>(x, ids, out);
}